// round 11
// baseline (speedup 1.0000x reference)
#include <cuda_runtime.h>
#include <cuda_fp16.h>
#include <math.h>

#define NN 100000
#define NF 64
#define NC 40
#define NE 1600000
#define NODES_BLK 64
#define NBLK_SCAN 98              // ceil(100000/1024)

// device-global scratch (BSS zero-init; g_cnt's zero state is restored by k_fused)
__device__ __align__(16) __half2 g_yh[NN * 32];  // y fp16, rows padded to 128B
__device__ __align__(16) float   g_z[NN * NC];   // z = x@Wr + b
__device__ int g_cnt[NN];        // degree histogram (zeroed at end of k_fused)
__device__ int g_off[NN];        // CSR offsets
__device__ int g_rank[NE];       // per-edge rank within dst bucket
__device__ int g_csr[NE];
__device__ int g_bsums[128];

// ---------------------------------------------------------------------------
__device__ __forceinline__ int clampn(int v) { return min(max(v, 0), NN - 1); }

__device__ __forceinline__ int detect_is64(const int* idx32) {
    int odd_nonzero = 0;
    for (int i = 1; i < 128; i += 2)
        if (idx32[i] != 0) odd_nonzero++;
    return (odd_nonzero == 0) ? 1 : 0;
}

// load 4 consecutive indices starting at element pos (pos % 4 == 0)
__device__ __forceinline__ void load_idx4(const void* raw, int is64, long long pos, int o[4]) {
    if (is64) {
        const longlong2* p = (const longlong2*)raw;
        longlong2 a = p[pos / 2];
        longlong2 b = p[pos / 2 + 1];
        o[0] = clampn((int)a.x); o[1] = clampn((int)a.y);
        o[2] = clampn((int)b.x); o[3] = clampn((int)b.y);
    } else {
        int4 v = ((const int4*)raw)[pos / 4];
        o[0] = clampn(v.x); o[1] = clampn(v.y);
        o[2] = clampn(v.z); o[3] = clampn(v.w);
    }
}

__device__ __forceinline__ unsigned cvt_tf32(float f) {
    unsigned r;
    asm("cvt.rna.tf32.f32 %0, %1;" : "=r"(r) : "f"(f));
    return r;
}

__device__ __forceinline__ void mma_tf32(float c[4], unsigned a0, unsigned a1,
                                         unsigned a2, unsigned a3,
                                         unsigned b0, unsigned b1) {
    asm("mma.sync.aligned.m16n8k8.row.col.f32.tf32.tf32.f32 "
        "{%0,%1,%2,%3}, {%4,%5,%6,%7}, {%8,%9}, {%0,%1,%2,%3};"
        : "+f"(c[0]), "+f"(c[1]), "+f"(c[2]), "+f"(c[3])
        : "r"(a0), "r"(a1), "r"(a2), "r"(a3), "r"(b0), "r"(b1));
}

// ---------------------------------------------------------------------------
// K1: dual GEMM on tensor cores (tf32 mma.sync, fp32 accumulate). Proven.
// ---------------------------------------------------------------------------
__global__ void __launch_bounds__(128) k_gemm(const float* __restrict__ x,
                                              const float* __restrict__ wl,
                                              const float* __restrict__ bl,
                                              const float* __restrict__ wr) {
    __shared__ unsigned s_x[NODES_BLK][68];
    __shared__ unsigned s_wl[NF * NC];
    __shared__ unsigned s_wr[NF * NC];
    __shared__ float    s_b[NC];

    const int tid = threadIdx.x;
    const int n0 = blockIdx.x * NODES_BLK;

    for (int i = tid; i < NF * NC; i += 128) {
        s_wl[i] = cvt_tf32(wl[i]);
        s_wr[i] = cvt_tf32(wr[i]);
    }
    if (tid < NC) s_b[tid] = bl[tid];

    for (int i = tid; i < NODES_BLK * 16; i += 128) {
        int node = i >> 4, kq = i & 15;
        int gn = n0 + node;
        float4 v = make_float4(0.f, 0.f, 0.f, 0.f);
        if (gn < NN) v = reinterpret_cast<const float4*>(x)[gn * 16 + kq];
        s_x[node][kq * 4 + 0] = cvt_tf32(v.x);
        s_x[node][kq * 4 + 1] = cvt_tf32(v.y);
        s_x[node][kq * 4 + 2] = cvt_tf32(v.z);
        s_x[node][kq * 4 + 3] = cvt_tf32(v.w);
    }
    __syncthreads();

    const int w = tid >> 5;
    const int lane = tid & 31;
    const int g = lane >> 2;
    const int t = lane & 3;
    const int wn = w * 16;

    float cy[5][4] = {}, cz[5][4] = {};
#pragma unroll
    for (int k0 = 0; k0 < NF; k0 += 8) {
        unsigned a0 = s_x[wn + g][k0 + t];
        unsigned a1 = s_x[wn + g + 8][k0 + t];
        unsigned a2 = s_x[wn + g][k0 + t + 4];
        unsigned a3 = s_x[wn + g + 8][k0 + t + 4];
#pragma unroll
        for (int nt = 0; nt < 5; nt++) {
            unsigned b0 = s_wl[(k0 + t) * NC + nt * 8 + g];
            unsigned b1 = s_wl[(k0 + t + 4) * NC + nt * 8 + g];
            mma_tf32(cy[nt], a0, a1, a2, a3, b0, b1);
            unsigned d0 = s_wr[(k0 + t) * NC + nt * 8 + g];
            unsigned d1 = s_wr[(k0 + t + 4) * NC + nt * 8 + g];
            mma_tf32(cz[nt], a0, a1, a2, a3, d0, d1);
        }
    }

#pragma unroll
    for (int nt = 0; nt < 5; nt++) {
        int c0 = nt * 8 + 2 * t;
        int nA = n0 + wn + g;
        int nB = nA + 8;
        if (nA < NN) {
            g_yh[nA * 32 + nt * 4 + t] = __floats2half2_rn(cy[nt][0], cy[nt][1]);
            float2 z = make_float2(cz[nt][0] + s_b[c0], cz[nt][1] + s_b[c0 + 1]);
            *reinterpret_cast<float2*>(&g_z[nA * NC + c0]) = z;
        }
        if (nB < NN) {
            g_yh[nB * 32 + nt * 4 + t] = __floats2half2_rn(cy[nt][2], cy[nt][3]);
            float2 z = make_float2(cz[nt][2] + s_b[c0], cz[nt][3] + s_b[c0 + 1]);
            *reinterpret_cast<float2*>(&g_z[nB * NC + c0]) = z;
        }
    }
    for (int i = tid; i < NODES_BLK * 12; i += 128) {
        int node = n0 + i / 12;
        int slot = 20 + i % 12;
        if (node < NN) g_yh[node * 32 + slot] = __floats2half2_rn(0.f, 0.f);
    }
}

// ---------------------------------------------------------------------------
// K2: degree histogram + per-edge rank (atomic return value), 4 edges/thread.
// ---------------------------------------------------------------------------
__global__ void __launch_bounds__(256) k_hist(const void* __restrict__ idx_raw) {
    __shared__ int s_is64;
    if (threadIdx.x == 0) s_is64 = detect_is64((const int*)idx_raw);
    __syncthreads();

    int t = blockIdx.x * 256 + threadIdx.x;
    long long e = (long long)t * 4;
    if (e >= NE) return;
    int d[4];
    load_idx4(idx_raw, s_is64, (long long)NE + e, d);
    int4 r;
    r.x = atomicAdd(&g_cnt[d[0]], 1);
    r.y = atomicAdd(&g_cnt[d[1]], 1);
    r.z = atomicAdd(&g_cnt[d[2]], 1);
    r.w = atomicAdd(&g_cnt[d[3]], 1);
    reinterpret_cast<int4*>(g_rank)[t] = r;
}

// K3a: 1024-elem exclusive scan per block
__global__ void __launch_bounds__(256) k_scan1() {
    __shared__ int s[256];
    int base = blockIdx.x * 1024 + threadIdx.x * 4;
    int v0 = (base + 0 < NN) ? g_cnt[base + 0] : 0;
    int v1 = (base + 1 < NN) ? g_cnt[base + 1] : 0;
    int v2 = (base + 2 < NN) ? g_cnt[base + 2] : 0;
    int v3 = (base + 3 < NN) ? g_cnt[base + 3] : 0;
    int tsum = v0 + v1 + v2 + v3;
    s[threadIdx.x] = tsum;
    __syncthreads();
#pragma unroll
    for (int off = 1; off < 256; off <<= 1) {
        int t = (threadIdx.x >= off) ? s[threadIdx.x - off] : 0;
        __syncthreads();
        s[threadIdx.x] += t;
        __syncthreads();
    }
    int excl = s[threadIdx.x] - tsum;
    if (base + 0 < NN) g_off[base + 0] = excl;
    if (base + 1 < NN) g_off[base + 1] = excl + v0;
    if (base + 2 < NN) g_off[base + 2] = excl + v0 + v1;
    if (base + 3 < NN) g_off[base + 3] = excl + v0 + v1 + v2;
    if (threadIdx.x == 255) g_bsums[blockIdx.x] = s[255];
}

// K3b: scan 98 block sums
__global__ void k_scan2() {
    __shared__ int s[128];
    int tid = threadIdx.x;
    int v = (tid < NBLK_SCAN) ? g_bsums[tid] : 0;
    s[tid] = v;
    __syncthreads();
#pragma unroll
    for (int off = 1; off < 128; off <<= 1) {
        int t = (tid >= off) ? s[tid - off] : 0;
        __syncthreads();
        s[tid] += t;
        __syncthreads();
    }
    if (tid < NBLK_SCAN) g_bsums[tid] = s[tid] - v;
}

// K3c: finalize offsets
__global__ void __launch_bounds__(256) k_scan3() {
    int n = blockIdx.x * 256 + threadIdx.x;
    if (n >= NN) return;
    g_off[n] += g_bsums[n >> 10];
}

// ---------------------------------------------------------------------------
// K4: CSR fill — ATOMIC-FREE: pos = off[dst] + rank[e].
// ---------------------------------------------------------------------------
__global__ void __launch_bounds__(256) k_fill(const void* __restrict__ idx_raw) {
    __shared__ int s_is64;
    if (threadIdx.x == 0) s_is64 = detect_is64((const int*)idx_raw);
    __syncthreads();

    int t = blockIdx.x * 256 + threadIdx.x;
    long long e = (long long)t * 4;
    if (e >= NE) return;
    int s[4], d[4];
    load_idx4(idx_raw, s_is64, e, s);
    load_idx4(idx_raw, s_is64, (long long)NE + e, d);
    int4 r = reinterpret_cast<const int4*>(g_rank)[t];
    g_csr[g_off[d[0]] + r.x] = s[0];
    g_csr[g_off[d[1]] + r.y] = s[1];
    g_csr[g_off[d[2]] + r.z] = s[2];
    g_csr[g_off[d[3]] + r.w] = s[3];
}

// ---------------------------------------------------------------------------
// K5: fused gather-mean + z + log_softmax. Warp per node. Inner loop
// unrolled x4 (independent shfl+LDG chains). Zeroes g_cnt at the end.
// ---------------------------------------------------------------------------
__global__ void __launch_bounds__(256) k_fused(float* __restrict__ out) {
    int gtid = blockIdx.x * 256 + threadIdx.x;
    int node = gtid >> 5;
    int lane = threadIdx.x & 31;
    if (node >= NN) return;

    int base = g_off[node];
    int deg  = g_cnt[node];

    float2 acc = make_float2(0.f, 0.f);
    for (int j0 = 0; j0 < deg; j0 += 32) {
        int e = (j0 + lane < deg) ? g_csr[base + j0 + lane] : 0;
        int m = min(32, deg - j0);
        int k = 0;
        for (; k + 4 <= m; k += 4) {
            int s0 = __shfl_sync(0xFFFFFFFFu, e, k + 0);
            int s1 = __shfl_sync(0xFFFFFFFFu, e, k + 1);
            int s2 = __shfl_sync(0xFFFFFFFFu, e, k + 2);
            int s3 = __shfl_sync(0xFFFFFFFFu, e, k + 3);
            float2 f0 = __half22float2(g_yh[s0 * 32 + lane]);
            float2 f1 = __half22float2(g_yh[s1 * 32 + lane]);
            float2 f2 = __half22float2(g_yh[s2 * 32 + lane]);
            float2 f3 = __half22float2(g_yh[s3 * 32 + lane]);
            acc.x += (f0.x + f1.x) + (f2.x + f3.x);
            acc.y += (f0.y + f1.y) + (f2.y + f3.y);
        }
        for (; k < m; k++) {
            int src = __shfl_sync(0xFFFFFFFFu, e, k);
            float2 f = __half22float2(g_yh[src * 32 + lane]);
            acc.x += f.x;
            acc.y += f.y;
        }
    }

    float inv = 1.0f / fmaxf((float)deg, 1.0f);
    const float NEG = -3.0e38f;
    bool valid = lane < 20;
    float2 z2 = valid ? reinterpret_cast<const float2*>(&g_z[node * NC])[lane]
                      : make_float2(0.f, 0.f);
    float va = valid ? fmaf(acc.x, inv, z2.x) : NEG;
    float vb = valid ? fmaf(acc.y, inv, z2.y) : NEG;

    float mx = fmaxf(va, vb);
#pragma unroll
    for (int off = 16; off > 0; off >>= 1)
        mx = fmaxf(mx, __shfl_xor_sync(0xFFFFFFFFu, mx, off));

    float s = valid ? (__expf(va - mx) + __expf(vb - mx)) : 0.0f;
#pragma unroll
    for (int off = 16; off > 0; off >>= 1)
        s += __shfl_xor_sync(0xFFFFFFFFu, s, off);

    float lse = mx + logf(s);
    if (valid) {
        float2 o = make_float2(va - lse, vb - lse);
        reinterpret_cast<float2*>(&out[node * NC])[lane] = o;
    }

    // restore the zero-invariant for the next execution (BSS starts zero)
    if (lane == 0) g_cnt[node] = 0;
}

extern "C" void kernel_launch(void* const* d_in, const int* in_sizes, int n_in,
                              void* d_out, int out_size) {
    const float* x   = (const float*)d_in[0];
    const void*  idx = d_in[1];
    const float* wl  = (const float*)d_in[2];
    const float* bl  = (const float*)d_in[3];
    const float* wr  = (const float*)d_in[4];
    float* out = (float*)d_out;

    k_gemm<<<(NN + NODES_BLK - 1) / NODES_BLK, 128>>>(x, wl, bl, wr);
    k_hist<<<(NE / 4 + 255) / 256, 256>>>(idx);
    k_scan1<<<NBLK_SCAN, 256>>>();
    k_scan2<<<1, 128>>>();
    k_scan3<<<(NN + 255) / 256, 256>>>();
    k_fill<<<(NE / 4 + 255) / 256, 256>>>(idx);
    k_fused<<<(NN * 32 + 255) / 256, 256>>>(out);
}